// round 14
// baseline (speedup 1.0000x reference)
#include <cuda_runtime.h>
#include <cuda_fp16.h>
#include <cstdint>
#include <cmath>

#define T_TOK 4096
#define NE    8
#define HDIM  2048
#define IDIM  4096
#define TOPK  2
#define NSLOT (T_TOK * TOPK)

#define TM    128
#define KC    64                 // k per stage (32 uints of half2 per A row)
#define SAH   36                 // A smem row stride (uints); 36%32=4 -> conflict-free
#define SBH1  136                // GEMM1 B kh-row stride (uints, N=128); 8t4+g conflict-free
#define SBH2  72                 // GEMM2 B kh-row stride (uints, N=64)

#define A_UINTS  (TM * SAH)            // 4608
#define B1_UINTS (32 * SBH1)           // 4352
#define B2_UINTS (32 * SBH2)           // 2304
#define STG1 (A_UINTS + B1_UINTS)      // 8960 uints
#define STG2 (A_UINTS + B2_UINTS)      // 6912 uints
#define SMEM1 (3 * STG1 * 4)           // 107520 B; 2 CTAs = 215KB < 228KB
#define SMEM2 (3 * STG2 * 4)           // 82944 B

// ---------------- scratch (static device memory; no allocations) ----------------
__device__ unsigned xh[(size_t)T_TOK * HDIM / 2];            // 16 MB  fp16 X, half2-packed
__device__ unsigned w13h[(size_t)NE * 1024 * 8192];          // 268 MB [e][kh][n] half2(k,k+1)
__device__ unsigned w2h[(size_t)NE * 2048 * 2048];           // 134 MB [e][kh][n]
__device__ unsigned acth[(size_t)NSLOT * IDIM / 2];          // 64 MB  fp16 activations
__device__ int   g_counts[NE];
__device__ int   g_pos[NE];
__device__ int   g_off[NE + 1];
__device__ int   g_tok_e[T_TOK * TOPK];
__device__ float g_tok_w[T_TOK * TOPK];
__device__ int   g_slot_tok[NSLOT];
__device__ float g_slot_w[NSLOT];

// ---------------- helpers ----------------
__device__ __forceinline__ unsigned h2(float a, float b) {
    __half2 h = __floats2half2_rn(a, b);
    return *(unsigned*)&h;
}
__device__ __forceinline__ void mma16(float* d, const unsigned* a, const unsigned* b) {
    asm volatile(
        "mma.sync.aligned.m16n8k16.row.col.f32.f16.f16.f32 "
        "{%0,%1,%2,%3}, {%4,%5,%6,%7}, {%8,%9}, {%0,%1,%2,%3};"
        : "+f"(d[0]), "+f"(d[1]), "+f"(d[2]), "+f"(d[3])
        : "r"(a[0]), "r"(a[1]), "r"(a[2]), "r"(a[3]), "r"(b[0]), "r"(b[1]));
}
__device__ __forceinline__ uint32_t s2u(const void* p) {
    uint32_t a;
    asm("{ .reg .u64 t; cvta.to.shared.u64 t, %1; cvt.u32.u64 %0, t; }" : "=r"(a) : "l"(p));
    return a;
}
__device__ __forceinline__ void cpa16(uint32_t dst, const void* src) {
    asm volatile("cp.async.cg.shared.global [%0], [%1], 16;" :: "r"(dst), "l"(src));
}
#define CP_COMMIT() asm volatile("cp.async.commit_group;" ::: "memory")
#define CP_WAIT1()  asm volatile("cp.async.wait_group 1;" ::: "memory")

// ---------------- small kernels ----------------
__global__ void k_init(float* __restrict__ out, int n) {
    int i = blockIdx.x * blockDim.x + threadIdx.x;
    if (i < n) out[i] = 0.f;
    if (i < NE) { g_counts[i] = 0; g_pos[i] = 0; }
}

__global__ void k_route(const float* __restrict__ logits) {
    int t = blockIdx.x * blockDim.x + threadIdx.x;
    if (t >= T_TOK) return;
    float p[NE];
    float mx = -1e30f;
#pragma unroll
    for (int e = 0; e < NE; e++) { p[e] = logits[t * NE + e]; mx = fmaxf(mx, p[e]); }
#pragma unroll
    for (int e = 0; e < NE; e++) p[e] = expf(p[e] - mx);
    int i0 = 0;
#pragma unroll
    for (int e = 1; e < NE; e++) if (p[e] > p[i0]) i0 = e;
    int i1 = (i0 == 0) ? 1 : 0;
#pragma unroll
    for (int e = 0; e < NE; e++) if (e != i0 && p[e] > p[i1]) i1 = e;
    float w0 = p[i0], w1 = p[i1];
    float s = w0 + w1;
    w0 /= s; w1 /= s;
    g_tok_e[t * 2] = i0;  g_tok_e[t * 2 + 1] = i1;
    g_tok_w[t * 2] = w0;  g_tok_w[t * 2 + 1] = w1;
    atomicAdd(&g_counts[i0], 1);
    atomicAdd(&g_counts[i1], 1);
}

__global__ void k_scan() {
    int acc = 0;
    for (int e = 0; e < NE; e++) { g_off[e] = acc; acc += g_counts[e]; }
    g_off[NE] = acc;
}

__global__ void k_scatter() {
    int t = blockIdx.x * blockDim.x + threadIdx.x;
    if (t >= T_TOK) return;
#pragma unroll
    for (int j = 0; j < TOPK; j++) {
        int e = g_tok_e[t * 2 + j];
        int pos = atomicAdd(&g_pos[e], 1);
        int s = g_off[e] + pos;
        g_slot_tok[s] = t;
        g_slot_w[s]   = g_tok_w[t * 2 + j];
    }
}

// ---------------- fp32 -> fp16 conversion kernels (one-time per launch) ----------------
__global__ void k_cvt_x(const float* __restrict__ X) {
    int i = blockIdx.x * blockDim.x + threadIdx.x;   // over T*H/4
    float4 v = *(const float4*)(X + 4 * (size_t)i);
    ((uint2*)xh)[i] = make_uint2(h2(v.x, v.y), h2(v.z, v.w));
}

// W13 [E][H][2I] -> w13h [e][kh=H/2][n=2I] half2(k, k+1); thread = 1 uint4 (4 n)
__global__ void k_cvt_w13(const float* __restrict__ W13) {
    int o = blockIdx.x * blockDim.x + threadIdx.x;   // NE*1024*2048
    int c = o & 2047;
    int row = o >> 11;
    int kh = row & 1023;
    int e = row >> 10;
    const float* s0 = W13 + ((size_t)e * 2048 + 2 * kh) * 8192 + 4 * c;
    float4 r0 = *(const float4*)s0;
    float4 r1 = *(const float4*)(s0 + 8192);
    ((uint4*)w13h)[o] = make_uint4(h2(r0.x, r1.x), h2(r0.y, r1.y), h2(r0.z, r1.z), h2(r0.w, r1.w));
}

// W2 [E][I][H] -> w2h [e][kh=I/2][n=H]
__global__ void k_cvt_w2(const float* __restrict__ W2) {
    int o = blockIdx.x * blockDim.x + threadIdx.x;   // NE*2048*512
    int c = o & 511;
    int row = o >> 9;
    int kh = row & 2047;
    int e = row >> 11;
    const float* s0 = W2 + ((size_t)e * 4096 + 2 * kh) * 2048 + 4 * c;
    float4 r0 = *(const float4*)s0;
    float4 r1 = *(const float4*)(s0 + 2048);
    ((uint4*)w2h)[o] = make_uint4(h2(r0.x, r1.x), h2(r0.y, r1.y), h2(r0.z, r1.z), h2(r0.w, r1.w));
}

// ---------------- GEMM1: acth[slot, n0:n0+64] = silu(X@W1)*(X@W3) ----------------
// 128 threads, 4 warps (2m x 2n), warp m64 x (32gate+32up); KC=64; 3-stage; 2 CTAs/SM
// grid: (32 m-tiles, IDIM/64 = 64 n-tiles, NE)
__global__ __launch_bounds__(128, 2) void k_gemm1() {
    int e = blockIdx.z;
    int m_beg = g_off[e], m_end = g_off[e + 1];
    int m0 = m_beg + blockIdx.x * TM;
    if (m0 >= m_end) return;
    int n0 = blockIdx.y * 64;

    extern __shared__ __align__(16) unsigned smem[];
    __shared__ int stok[TM];

    int tid = threadIdx.x, warp = tid >> 5, lane = tid & 31;
    int wm = warp >> 1, wn = warp & 1;
    int g = lane >> 2, t4 = lane & 3;

    {
        int gr = m0 + tid;
        stok[tid] = (gr < m_end) ? g_slot_tok[gr] : -1;
    }
    __syncthreads();

    int tok = stok[tid];
    if (tok < 0) tok = stok[0];                       // valid row; garbage masked at epilogue
    const unsigned* asrc = xh + (size_t)tok * (HDIM / 2);
    int kh = tid >> 2;                                // 0..31 (stage kh-row)
    int c4 = tid & 3;                                 // 0..3
    const unsigned* bsrc = w13h + ((size_t)e * 1024 + kh) * 8192 + n0;
    uint32_t smemu = s2u(smem);
    uint32_t aDst = smemu + (tid * SAH) * 4;          // row tid
    uint32_t bDst = smemu + (A_UINTS + kh * SBH1) * 4;

#define G1_ISSUE(kc_, s_) do {                                                  \
    uint32_t _o = (uint32_t)(s_) * (STG1 * 4);                                  \
    const unsigned* _a = asrc + (kc_) * 32;                                     \
    _Pragma("unroll")                                                           \
    for (int _j = 0; _j < 8; _j++) cpa16(aDst + _o + 16 * _j, _a + 4 * _j);     \
    const unsigned* _w = bsrc + (size_t)(kc_) * (32 * 8192);                    \
    _Pragma("unroll")                                                           \
    for (int _j = 0; _j < 8; _j++) {                                            \
        int _p4 = c4 + 4 * _j;                                                  \
        int _nc = (_p4 < 16) ? 4 * _p4 : (IDIM - 64 + 4 * _p4);                 \
        cpa16(bDst + _o + 16 * _p4, _w + _nc);                                  \
    }                                                                           \
} while (0)

    float accG[4][4][4], accU[4][4][4];
#pragma unroll
    for (int mt = 0; mt < 4; mt++)
#pragma unroll
        for (int q = 0; q < 4; q++)
#pragma unroll
            for (int x = 0; x < 4; x++) { accG[mt][q][x] = 0.f; accU[mt][q][x] = 0.f; }

    const int NI = HDIM / KC;   // 32
    G1_ISSUE(0, 0); CP_COMMIT();
    G1_ISSUE(1, 1); CP_COMMIT();

    int sc = 0, si = 2;
    for (int kc = 0; kc < NI; kc++) {
        CP_WAIT1();
        __syncthreads();
        if (kc + 2 < NI) G1_ISSUE(kc + 2, si);
        CP_COMMIT();
        si = (si == 2) ? 0 : si + 1;

        const unsigned* cA = smem + sc * STG1;
        const unsigned* cB = cA + A_UINTS;
        sc = (sc == 2) ? 0 : sc + 1;

#pragma unroll
        for (int ks = 0; ks < 4; ks++) {
            int khb = ks * 8;
            unsigned af[4][4];
#pragma unroll
            for (int mt = 0; mt < 4; mt++) {
                int r = (wm * 64 + mt * 16 + g) * SAH + khb + t4;
                af[mt][0] = cA[r];
                af[mt][1] = cA[r + 8 * SAH];
                af[mt][2] = cA[r + 4];
                af[mt][3] = cA[r + 8 * SAH + 4];
            }
            int rb0 = (khb + t4) * SBH1, rb1 = (khb + t4 + 4) * SBH1;
#pragma unroll
            for (int q = 0; q < 4; q++) {
                int cbg = wn * 32 + q * 8 + g;
                unsigned bg[2], bu[2];
                bg[0] = cB[rb0 + cbg];       bg[1] = cB[rb1 + cbg];
                bu[0] = cB[rb0 + cbg + 64];  bu[1] = cB[rb1 + cbg + 64];
#pragma unroll
                for (int mt = 0; mt < 4; mt++) {
                    mma16(accG[mt][q], af[mt], bg);
                    mma16(accU[mt][q], af[mt], bu);
                }
            }
        }
    }
#undef G1_ISSUE

    // epilogue: silu(gate)*up -> acth (half2 stores)
#pragma unroll
    for (int mt = 0; mt < 4; mt++) {
        int R0 = m0 + wm * 64 + mt * 16 + g;
        int R1 = R0 + 8;
#pragma unroll
        for (int q = 0; q < 4; q++) {
            int col = n0 + wn * 32 + q * 8 + t4 * 2;
            float* G = accG[mt][q];
            float* U = accU[mt][q];
            if (R0 < m_end) {
                float a0 = G[0] / (1.f + expf(-G[0])) * U[0];
                float a1 = G[1] / (1.f + expf(-G[1])) * U[1];
                ((__half2*)acth)[(size_t)R0 * (IDIM / 2) + (col >> 1)] = __floats2half2_rn(a0, a1);
            }
            if (R1 < m_end) {
                float a2 = G[2] / (1.f + expf(-G[2])) * U[2];
                float a3 = G[3] / (1.f + expf(-G[3])) * U[3];
                ((__half2*)acth)[(size_t)R1 * (IDIM / 2) + (col >> 1)] = __floats2half2_rn(a2, a3);
            }
        }
    }
}

// ---------------- GEMM2: out[tok] += w * (acth[slot] @ W2[e]) ----------------
// 128 threads, 4 warps (2m x 2n), warp m64 x n32; block 128x64; KC=64; 3-stage
// grid: (32 m-tiles, HDIM/64 = 32 n-tiles, NE)  -- small n-tiles for tail efficiency
__global__ __launch_bounds__(128, 2) void k_gemm2(float* __restrict__ out) {
    int e = blockIdx.z;
    int m_beg = g_off[e], m_end = g_off[e + 1];
    int m0 = m_beg + blockIdx.x * TM;
    if (m0 >= m_end) return;
    int n0 = blockIdx.y * 64;

    extern __shared__ __align__(16) unsigned smem[];
    __shared__ int   stok[TM];
    __shared__ float swt[TM];

    int tid = threadIdx.x, warp = tid >> 5, lane = tid & 31;
    int wm = warp >> 1, wn = warp & 1;
    int g = lane >> 2, t4 = lane & 3;

    {
        int gr = m0 + tid;
        bool v = (gr < m_end);
        stok[tid] = v ? g_slot_tok[gr] : 0;
        swt[tid]  = v ? g_slot_w[gr]   : 0.f;
    }
    __syncthreads();

    int arow = (m0 + tid < m_end) ? (m0 + tid) : m0;
    const unsigned* asrc = acth + (size_t)arow * (IDIM / 2);
    int kh = tid >> 2;
    int c4 = tid & 3;
    const unsigned* bsrc = w2h + ((size_t)e * 2048 + kh) * 2048 + n0;
    uint32_t smemu = s2u(smem);
    uint32_t aDst = smemu + (tid * SAH) * 4;
    uint32_t bDst = smemu + (A_UINTS + kh * SBH2) * 4;

#define G2_ISSUE(kc_, s_) do {                                                  \
    uint32_t _o = (uint32_t)(s_) * (STG2 * 4);                                  \
    const unsigned* _a = asrc + (kc_) * 32;                                     \
    _Pragma("unroll")                                                           \
    for (int _j = 0; _j < 8; _j++) cpa16(aDst + _o + 16 * _j, _a + 4 * _j);     \
    const unsigned* _w = bsrc + (size_t)(kc_) * (32 * 2048);                    \
    _Pragma("unroll")                                                           \
    for (int _j = 0; _j < 4; _j++) {                                            \
        int _p4 = c4 + 4 * _j;                                                  \
        cpa16(bDst + _o + 16 * _p4, _w + 4 * _p4);                              \
    }                                                                           \
} while (0)

    float acc[4][4][4];
#pragma unroll
    for (int mt = 0; mt < 4; mt++)
#pragma unroll
        for (int q = 0; q < 4; q++)
#pragma unroll
            for (int x = 0; x < 4; x++) acc[mt][q][x] = 0.f;

    const int NI = IDIM / KC;   // 64
    G2_ISSUE(0, 0); CP_COMMIT();
    G2_ISSUE(1, 1); CP_COMMIT();

    int sc = 0, si = 2;
    for (int kc = 0; kc < NI; kc++) {
        CP_WAIT1();
        __syncthreads();
        if (kc + 2 < NI) G2_ISSUE(kc + 2, si);
        CP_COMMIT();
        si = (si == 2) ? 0 : si + 1;

        const unsigned* cA = smem + sc * STG2;
        const unsigned* cB = cA + A_UINTS;
        sc = (sc == 2) ? 0 : sc + 1;

#pragma unroll
        for (int ks = 0; ks < 4; ks++) {
            int khb = ks * 8;
            unsigned af[4][4];
#pragma unroll
            for (int mt = 0; mt < 4; mt++) {
                int r = (wm * 64 + mt * 16 + g) * SAH + khb + t4;
                af[mt][0] = cA[r];
                af[mt][1] = cA[r + 8 * SAH];
                af[mt][2] = cA[r + 4];
                af[mt][3] = cA[r + 8 * SAH + 4];
            }
            int rb0 = (khb + t4) * SBH2, rb1 = (khb + t4 + 4) * SBH2;
#pragma unroll
            for (int q = 0; q < 4; q++) {
                int cb = wn * 32 + q * 8 + g;
                unsigned bf[2];
                bf[0] = cB[rb0 + cb];
                bf[1] = cB[rb1 + cb];
#pragma unroll
                for (int mt = 0; mt < 4; mt++)
                    mma16(acc[mt][q], af[mt], bf);
            }
        }
    }
#undef G2_ISSUE

    // epilogue: weighted atomic scatter into out
#pragma unroll
    for (int mt = 0; mt < 4; mt++) {
        int L0 = wm * 64 + mt * 16 + g;
        int L1 = L0 + 8;
        bool v0 = (m0 + L0 < m_end);
        bool v1 = (m0 + L1 < m_end);
        int   tk0 = stok[L0], tk1 = stok[L1];
        float w0 = swt[L0],  w1 = swt[L1];
#pragma unroll
        for (int q = 0; q < 4; q++) {
            int col = n0 + wn * 32 + q * 8 + t4 * 2;
            float* d = acc[mt][q];
            if (v0) {
                atomicAdd(&out[(size_t)tk0 * HDIM + col],     w0 * d[0]);
                atomicAdd(&out[(size_t)tk0 * HDIM + col + 1], w0 * d[1]);
            }
            if (v1) {
                atomicAdd(&out[(size_t)tk1 * HDIM + col],     w1 * d[2]);
                atomicAdd(&out[(size_t)tk1 * HDIM + col + 1], w1 * d[3]);
            }
        }
    }
}

// ---------------- launch ----------------
extern "C" void kernel_launch(void* const* d_in, const int* in_sizes, int n_in,
                              void* d_out, int out_size) {
    const float* X      = (const float*)d_in[0];
    const float* logits = (const float*)d_in[1];
    const float* W13    = (const float*)d_in[2];
    const float* W2     = (const float*)d_in[3];
    float* out = (float*)d_out;

    static bool attr_done = false;
    if (!attr_done) {
        cudaFuncSetAttribute(k_gemm1, cudaFuncAttributeMaxDynamicSharedMemorySize, SMEM1);
        cudaFuncSetAttribute(k_gemm2, cudaFuncAttributeMaxDynamicSharedMemorySize, SMEM2);
        attr_done = true;
    }

    int n_out = T_TOK * HDIM;
    k_init<<<(n_out + 1023) / 1024, 1024>>>(out, n_out);
    k_route<<<(T_TOK + 255) / 256, 256>>>(logits);
    k_scan<<<1, 1>>>();
    k_scatter<<<(T_TOK + 255) / 256, 256>>>();

    k_cvt_x<<<T_TOK * HDIM / 4 / 256, 256>>>(X);
    k_cvt_w13<<<NE * 1024 * 2048 / 256, 256>>>(W13);
    k_cvt_w2<<<NE * 2048 * 512 / 256, 256>>>(W2);

    k_gemm1<<<dim3(32, IDIM / 64, NE), 128, SMEM1>>>();
    k_gemm2<<<dim3(32, HDIM / 64, NE), 128, SMEM2>>>(out);
}

// round 15
// speedup vs baseline: 1.1197x; 1.1197x over previous
#include <cuda_runtime.h>
#include <cuda_fp16.h>
#include <cstdint>
#include <cmath>

#define T_TOK 4096
#define NE    8
#define HDIM  2048
#define IDIM  4096
#define TOPK  2
#define NSLOT (T_TOK * TOPK)

#define TM    128
#define KC    32
#define SAH   20     // A smem row stride (uints = half2); STS/LDS conflict-free
#define SBH   136    // B smem kh-row stride (uints); 8kh+g pattern conflict-free

#define A_UINTS (TM * SAH)        // 2560
#define B_UINTS (16 * SBH)        // 2176
#define STG     (A_UINTS + B_UINTS)
#define NSTAGE  3
#define SMEM_BYTES (NSTAGE * STG * 4)   // 56832; 2 CTAs/SM = 113664 < 228KB

// ---------------- scratch (static device memory; no allocations) ----------------
__device__ unsigned xh[(size_t)T_TOK * HDIM / 2];            // 16 MB  fp16 X, half2-packed
__device__ unsigned w13h[(size_t)NE * 1024 * 8192];          // 268 MB [e][kh][n] half2(k,k+1)
__device__ unsigned w2h[(size_t)NE * 2048 * 2048];           // 134 MB [e][kh][n]
__device__ unsigned acth[(size_t)NSLOT * IDIM / 2];          // 64 MB  fp16 activations
__device__ int   g_counts[NE];
__device__ int   g_pos[NE];
__device__ int   g_off[NE + 1];
__device__ int   g_tok_e[T_TOK * TOPK];
__device__ float g_tok_w[T_TOK * TOPK];
__device__ int   g_slot_tok[NSLOT];
__device__ float g_slot_w[NSLOT];

// ---------------- helpers ----------------
__device__ __forceinline__ unsigned h2(float a, float b) {
    __half2 h = __floats2half2_rn(a, b);
    return *(unsigned*)&h;
}
__device__ __forceinline__ void mma16(float* d, const unsigned* a, const unsigned* b) {
    asm volatile(
        "mma.sync.aligned.m16n8k16.row.col.f32.f16.f16.f32 "
        "{%0,%1,%2,%3}, {%4,%5,%6,%7}, {%8,%9}, {%0,%1,%2,%3};"
        : "+f"(d[0]), "+f"(d[1]), "+f"(d[2]), "+f"(d[3])
        : "r"(a[0]), "r"(a[1]), "r"(a[2]), "r"(a[3]), "r"(b[0]), "r"(b[1]));
}
__device__ __forceinline__ uint32_t s2u(const void* p) {
    uint32_t a;
    asm("{ .reg .u64 t; cvta.to.shared.u64 t, %1; cvt.u32.u64 %0, t; }" : "=r"(a) : "l"(p));
    return a;
}
__device__ __forceinline__ void cpa16(uint32_t dst, const void* src) {
    asm volatile("cp.async.cg.shared.global [%0], [%1], 16;" :: "r"(dst), "l"(src));
}
#define CP_COMMIT() asm volatile("cp.async.commit_group;" ::: "memory")
#define CP_WAIT1()  asm volatile("cp.async.wait_group 1;" ::: "memory")

// ---------------- small kernels ----------------
__global__ void k_init(float* __restrict__ out, int n) {
    int i = blockIdx.x * blockDim.x + threadIdx.x;
    if (i < n) out[i] = 0.f;
    if (i < NE) { g_counts[i] = 0; g_pos[i] = 0; }
}

__global__ void k_route(const float* __restrict__ logits) {
    int t = blockIdx.x * blockDim.x + threadIdx.x;
    if (t >= T_TOK) return;
    float p[NE];
    float mx = -1e30f;
#pragma unroll
    for (int e = 0; e < NE; e++) { p[e] = logits[t * NE + e]; mx = fmaxf(mx, p[e]); }
#pragma unroll
    for (int e = 0; e < NE; e++) p[e] = expf(p[e] - mx);
    int i0 = 0;
#pragma unroll
    for (int e = 1; e < NE; e++) if (p[e] > p[i0]) i0 = e;
    int i1 = (i0 == 0) ? 1 : 0;
#pragma unroll
    for (int e = 0; e < NE; e++) if (e != i0 && p[e] > p[i1]) i1 = e;
    float w0 = p[i0], w1 = p[i1];
    float s = w0 + w1;
    w0 /= s; w1 /= s;
    g_tok_e[t * 2] = i0;  g_tok_e[t * 2 + 1] = i1;
    g_tok_w[t * 2] = w0;  g_tok_w[t * 2 + 1] = w1;
    atomicAdd(&g_counts[i0], 1);
    atomicAdd(&g_counts[i1], 1);
}

__global__ void k_scan() {
    int acc = 0;
    for (int e = 0; e < NE; e++) { g_off[e] = acc; acc += g_counts[e]; }
    g_off[NE] = acc;
}

__global__ void k_scatter() {
    int t = blockIdx.x * blockDim.x + threadIdx.x;
    if (t >= T_TOK) return;
#pragma unroll
    for (int j = 0; j < TOPK; j++) {
        int e = g_tok_e[t * 2 + j];
        int pos = atomicAdd(&g_pos[e], 1);
        int s = g_off[e] + pos;
        g_slot_tok[s] = t;
        g_slot_w[s]   = g_tok_w[t * 2 + j];
    }
}

// ---------------- fp32 -> fp16 conversion kernels (one-time per launch) ----------------
__global__ void k_cvt_x(const float* __restrict__ X) {
    int i = blockIdx.x * blockDim.x + threadIdx.x;   // over T*H/4
    float4 v = *(const float4*)(X + 4 * (size_t)i);
    ((uint2*)xh)[i] = make_uint2(h2(v.x, v.y), h2(v.z, v.w));
}

// W13 [E][H][2I] -> w13h [e][kh=H/2][n=2I] half2(k, k+1); thread = 1 uint4 (4 n)
__global__ void k_cvt_w13(const float* __restrict__ W13) {
    int o = blockIdx.x * blockDim.x + threadIdx.x;   // NE*1024*2048
    int c = o & 2047;
    int row = o >> 11;
    int kh = row & 1023;
    int e = row >> 10;
    const float* s0 = W13 + ((size_t)e * 2048 + 2 * kh) * 8192 + 4 * c;
    float4 r0 = *(const float4*)s0;
    float4 r1 = *(const float4*)(s0 + 8192);
    ((uint4*)w13h)[o] = make_uint4(h2(r0.x, r1.x), h2(r0.y, r1.y), h2(r0.z, r1.z), h2(r0.w, r1.w));
}

// W2 [E][I][H] -> w2h [e][kh=I/2][n=H]
__global__ void k_cvt_w2(const float* __restrict__ W2) {
    int o = blockIdx.x * blockDim.x + threadIdx.x;   // NE*2048*512
    int c = o & 511;
    int row = o >> 9;
    int kh = row & 2047;
    int e = row >> 11;
    const float* s0 = W2 + ((size_t)e * 4096 + 2 * kh) * 2048 + 4 * c;
    float4 r0 = *(const float4*)s0;
    float4 r1 = *(const float4*)(s0 + 2048);
    ((uint4*)w2h)[o] = make_uint4(h2(r0.x, r1.x), h2(r0.y, r1.y), h2(r0.z, r1.z), h2(r0.w, r1.w));
}

// ---------------- GEMM1: acth[slot, n0:n0+64] = silu(X@W1)*(X@W3) ----------------
// 128 threads, 4 warps (2m x 2n), warp m64 x (32gate+32up); cp.async 3-stage; 2 CTAs/SM
// grid: (32 m-tiles, IDIM/64 = 64 n-tiles, NE)
__global__ __launch_bounds__(128, 2) void k_gemm1() {
    int e = blockIdx.z;
    int m_beg = g_off[e], m_end = g_off[e + 1];
    int m0 = m_beg + blockIdx.x * TM;
    if (m0 >= m_end) return;
    int n0 = blockIdx.y * 64;

    extern __shared__ __align__(16) unsigned smem[];
    __shared__ int stok[TM];

    int tid = threadIdx.x, warp = tid >> 5, lane = tid & 31;
    int wm = warp >> 1, wn = warp & 1;
    int g = lane >> 2, t4 = lane & 3;

    {
        int gr = m0 + tid;
        stok[tid] = (gr < m_end) ? g_slot_tok[gr] : -1;
    }
    __syncthreads();

    int tok = stok[tid];
    if (tok < 0) tok = stok[0];                       // valid row; garbage masked at epilogue
    const unsigned* asrc = xh + (size_t)tok * (HDIM / 2);
    int kh = (tid & 3) | ((tid >> 5) << 2);           // 0..15
    int c4 = (tid >> 2) & 7;                          // 0..7
    const unsigned* bsrc = w13h + ((size_t)e * 1024 + kh) * 8192 + n0;
    uint32_t smemu = s2u(smem);
    uint32_t aDst = smemu + (tid * SAH) * 4;
    uint32_t bDst = smemu + (A_UINTS + kh * SBH) * 4;

#define G1_ISSUE(kc_, s_) do {                                                  \
    uint32_t _o = (uint32_t)(s_) * (STG * 4);                                   \
    const unsigned* _a = asrc + (kc_) * 16;                                     \
    cpa16(aDst + _o,      _a);                                                  \
    cpa16(aDst + _o + 16, _a + 4);                                              \
    cpa16(aDst + _o + 32, _a + 8);                                              \
    cpa16(aDst + _o + 48, _a + 12);                                             \
    const unsigned* _w = bsrc + (size_t)(kc_) * (16 * 8192);                    \
    _Pragma("unroll")                                                           \
    for (int _j = 0; _j < 4; _j++) {                                            \
        int _p4 = c4 + 8 * _j;                                                  \
        int _nc = (_p4 < 16) ? 4 * _p4 : (IDIM - 64 + 4 * _p4);                 \
        cpa16(bDst + _o + 16 * _p4, _w + _nc);                                  \
    }                                                                           \
} while (0)

    float accG[4][4][4], accU[4][4][4];
#pragma unroll
    for (int mt = 0; mt < 4; mt++)
#pragma unroll
        for (int q = 0; q < 4; q++)
#pragma unroll
            for (int x = 0; x < 4; x++) { accG[mt][q][x] = 0.f; accU[mt][q][x] = 0.f; }

    const int NI = HDIM / KC;   // 64
    G1_ISSUE(0, 0); CP_COMMIT();
    G1_ISSUE(1, 1); CP_COMMIT();

    int sc = 0, si = 2;
    for (int kc = 0; kc < NI; kc++) {
        CP_WAIT1();
        __syncthreads();
        if (kc + 2 < NI) G1_ISSUE(kc + 2, si);
        CP_COMMIT();
        si = (si == 2) ? 0 : si + 1;

        const unsigned* cA = smem + sc * STG;
        const unsigned* cB = cA + A_UINTS;
        sc = (sc == 2) ? 0 : sc + 1;

#pragma unroll
        for (int ks = 0; ks < 2; ks++) {
            int khb = ks * 8;
            unsigned af[4][4];
#pragma unroll
            for (int mt = 0; mt < 4; mt++) {
                int r = (wm * 64 + mt * 16 + g) * SAH + khb + t4;
                af[mt][0] = cA[r];
                af[mt][1] = cA[r + 8 * SAH];
                af[mt][2] = cA[r + 4];
                af[mt][3] = cA[r + 8 * SAH + 4];
            }
            int rb0 = (khb + t4) * SBH, rb1 = (khb + t4 + 4) * SBH;
#pragma unroll
            for (int q = 0; q < 4; q++) {
                int cbg = wn * 32 + q * 8 + g;
                unsigned bg[2], bu[2];
                bg[0] = cB[rb0 + cbg];       bg[1] = cB[rb1 + cbg];
                bu[0] = cB[rb0 + cbg + 64];  bu[1] = cB[rb1 + cbg + 64];
#pragma unroll
                for (int mt = 0; mt < 4; mt++) {
                    mma16(accG[mt][q], af[mt], bg);
                    mma16(accU[mt][q], af[mt], bu);
                }
            }
        }
    }
#undef G1_ISSUE

    // epilogue: silu(gate)*up -> acth (half2 stores)
#pragma unroll
    for (int mt = 0; mt < 4; mt++) {
        int R0 = m0 + wm * 64 + mt * 16 + g;
        int R1 = R0 + 8;
#pragma unroll
        for (int q = 0; q < 4; q++) {
            int col = n0 + wn * 32 + q * 8 + t4 * 2;
            float* G = accG[mt][q];
            float* U = accU[mt][q];
            if (R0 < m_end) {
                float a0 = G[0] / (1.f + expf(-G[0])) * U[0];
                float a1 = G[1] / (1.f + expf(-G[1])) * U[1];
                ((__half2*)acth)[(size_t)R0 * (IDIM / 2) + (col >> 1)] = __floats2half2_rn(a0, a1);
            }
            if (R1 < m_end) {
                float a2 = G[2] / (1.f + expf(-G[2])) * U[2];
                float a3 = G[3] / (1.f + expf(-G[3])) * U[3];
                ((__half2*)acth)[(size_t)R1 * (IDIM / 2) + (col >> 1)] = __floats2half2_rn(a2, a3);
            }
        }
    }
}

// ---------------- GEMM2: out[tok] += w * (acth[slot] @ W2[e]) ----------------
// 128 threads, 4 warps (2m x 2n), warp m64 x n64; block 128x128; cp.async 3-stage
// grid: (32 m-tiles, HDIM/128 = 16 n-tiles, NE)
__global__ __launch_bounds__(128, 2) void k_gemm2(float* __restrict__ out) {
    int e = blockIdx.z;
    int m_beg = g_off[e], m_end = g_off[e + 1];
    int m0 = m_beg + blockIdx.x * TM;
    if (m0 >= m_end) return;
    int n0 = blockIdx.y * 128;

    extern __shared__ __align__(16) unsigned smem[];
    __shared__ int   stok[TM];
    __shared__ float swt[TM];

    int tid = threadIdx.x, warp = tid >> 5, lane = tid & 31;
    int wm = warp >> 1, wn = warp & 1;
    int g = lane >> 2, t4 = lane & 3;

    {
        int gr = m0 + tid;
        bool v = (gr < m_end);
        stok[tid] = v ? g_slot_tok[gr] : 0;
        swt[tid]  = v ? g_slot_w[gr]   : 0.f;
    }
    __syncthreads();

    int arow = (m0 + tid < m_end) ? (m0 + tid) : m0;
    const unsigned* asrc = acth + (size_t)arow * (IDIM / 2);
    int kh = (tid & 3) | ((tid >> 5) << 2);
    int c4 = (tid >> 2) & 7;
    const unsigned* bsrc = w2h + ((size_t)e * 2048 + kh) * 2048 + n0;
    uint32_t smemu = s2u(smem);
    uint32_t aDst = smemu + (tid * SAH) * 4;
    uint32_t bDst = smemu + (A_UINTS + kh * SBH) * 4;

#define G2_ISSUE(kc_, s_) do {                                                  \
    uint32_t _o = (uint32_t)(s_) * (STG * 4);                                   \
    const unsigned* _a = asrc + (kc_) * 16;                                     \
    cpa16(aDst + _o,      _a);                                                  \
    cpa16(aDst + _o + 16, _a + 4);                                              \
    cpa16(aDst + _o + 32, _a + 8);                                              \
    cpa16(aDst + _o + 48, _a + 12);                                             \
    const unsigned* _w = bsrc + (size_t)(kc_) * (16 * 2048);                    \
    _Pragma("unroll")                                                           \
    for (int _j = 0; _j < 4; _j++) {                                            \
        int _p4 = c4 + 8 * _j;                                                  \
        cpa16(bDst + _o + 16 * _p4, _w + 4 * _p4);                              \
    }                                                                           \
} while (0)

    float acc[4][8][4];
#pragma unroll
    for (int mt = 0; mt < 4; mt++)
#pragma unroll
        for (int q = 0; q < 8; q++)
#pragma unroll
            for (int x = 0; x < 4; x++) acc[mt][q][x] = 0.f;

    const int NI = IDIM / KC;   // 128
    G2_ISSUE(0, 0); CP_COMMIT();
    G2_ISSUE(1, 1); CP_COMMIT();

    int sc = 0, si = 2;
    for (int kc = 0; kc < NI; kc++) {
        CP_WAIT1();
        __syncthreads();
        if (kc + 2 < NI) G2_ISSUE(kc + 2, si);
        CP_COMMIT();
        si = (si == 2) ? 0 : si + 1;

        const unsigned* cA = smem + sc * STG;
        const unsigned* cB = cA + A_UINTS;
        sc = (sc == 2) ? 0 : sc + 1;

#pragma unroll
        for (int ks = 0; ks < 2; ks++) {
            int khb = ks * 8;
            unsigned af[4][4];
#pragma unroll
            for (int mt = 0; mt < 4; mt++) {
                int r = (wm * 64 + mt * 16 + g) * SAH + khb + t4;
                af[mt][0] = cA[r];
                af[mt][1] = cA[r + 8 * SAH];
                af[mt][2] = cA[r + 4];
                af[mt][3] = cA[r + 8 * SAH + 4];
            }
            int rb0 = (khb + t4) * SBH, rb1 = (khb + t4 + 4) * SBH;
#pragma unroll
            for (int q = 0; q < 8; q++) {
                int cb = wn * 64 + q * 8 + g;
                unsigned bf[2];
                bf[0] = cB[rb0 + cb];
                bf[1] = cB[rb1 + cb];
#pragma unroll
                for (int mt = 0; mt < 4; mt++)
                    mma16(acc[mt][q], af[mt], bf);
            }
        }
    }
#undef G2_ISSUE

    // epilogue: weighted atomic scatter into out
#pragma unroll
    for (int mt = 0; mt < 4; mt++) {
        int L0 = wm * 64 + mt * 16 + g;
        int L1 = L0 + 8;
        bool v0 = (m0 + L0 < m_end);
        bool v1 = (m0 + L1 < m_end);
        int   tk0 = stok[L0], tk1 = stok[L1];
        float w0 = swt[L0],  w1 = swt[L1];
#pragma unroll
        for (int q = 0; q < 8; q++) {
            int col = n0 + wn * 64 + q * 8 + t4 * 2;
            float* d = acc[mt][q];
            if (v0) {
                atomicAdd(&out[(size_t)tk0 * HDIM + col],     w0 * d[0]);
                atomicAdd(&out[(size_t)tk0 * HDIM + col + 1], w0 * d[1]);
            }
            if (v1) {
                atomicAdd(&out[(size_t)tk1 * HDIM + col],     w1 * d[2]);
                atomicAdd(&out[(size_t)tk1 * HDIM + col + 1], w1 * d[3]);
            }
        }
    }
}

// ---------------- launch: fork-join multi-stream graph ----------------
extern "C" void kernel_launch(void* const* d_in, const int* in_sizes, int n_in,
                              void* d_out, int out_size) {
    const float* X      = (const float*)d_in[0];
    const float* logits = (const float*)d_in[1];
    const float* W13    = (const float*)d_in[2];
    const float* W2     = (const float*)d_in[3];
    float* out = (float*)d_out;

    static bool init_done = false;
    static cudaStream_t s1 = 0, s2 = 0;
    static cudaEvent_t ev0 = 0, ev1 = 0, ev2 = 0;
    if (!init_done) {
        cudaFuncSetAttribute(k_gemm1, cudaFuncAttributeMaxDynamicSharedMemorySize, SMEM_BYTES);
        cudaFuncSetAttribute(k_gemm2, cudaFuncAttributeMaxDynamicSharedMemorySize, SMEM_BYTES);
        cudaStreamCreateWithFlags(&s1, cudaStreamNonBlocking);
        cudaStreamCreateWithFlags(&s2, cudaStreamNonBlocking);
        cudaEventCreateWithFlags(&ev0, cudaEventDisableTiming);
        cudaEventCreateWithFlags(&ev1, cudaEventDisableTiming);
        cudaEventCreateWithFlags(&ev2, cudaEventDisableTiming);
        init_done = true;
    }

    // fork
    cudaEventRecord(ev0, 0);
    cudaStreamWaitEvent(s1, ev0, 0);
    cudaStreamWaitEvent(s2, ev0, 0);

    // branch s1: X + W13 conversion (needed by gemm1)
    k_cvt_x<<<T_TOK * HDIM / 4 / 256, 256, 0, s1>>>(X);
    k_cvt_w13<<<NE * 1024 * 2048 / 256, 256, 0, s1>>>(W13);
    cudaEventRecord(ev1, s1);

    // branch s2: W2 conversion (needed by gemm2 only; overlaps routing + gemm1)
    k_cvt_w2<<<NE * 2048 * 512 / 256, 256, 0, s2>>>(W2);
    cudaEventRecord(ev2, s2);

    // main stream: routing chain
    int n_out = T_TOK * HDIM;
    k_init<<<(n_out + 1023) / 1024, 1024>>>(out, n_out);
    k_route<<<(T_TOK + 255) / 256, 256>>>(logits);
    k_scan<<<1, 1>>>();
    k_scatter<<<(T_TOK + 255) / 256, 256>>>();

    // join s1, run gemm1
    cudaStreamWaitEvent(0, ev1, 0);
    k_gemm1<<<dim3(32, IDIM / 64, NE), 128, SMEM_BYTES>>>();

    // join s2, run gemm2
    cudaStreamWaitEvent(0, ev2, 0);
    k_gemm2<<<dim3(32, HDIM / 128, NE), 128, SMEM_BYTES>>>(out);
}